// round 7
// baseline (speedup 1.0000x reference)
#include <cuda_runtime.h>
#include <cuda_bf16.h>
#include <cstdint>

#define NLEV 16
#define TBL 524288u
#define PRIME_Y 2654435761u
#define NPTS (1 << 20)

// floor(16 * 2^(7l/15)), l = 0..15 — matches numpy fp64 _resolutions()
__constant__ float c_res[NLEV] = {
    16.f, 22.f, 30.f, 42.f, 58.f, 80.f, 111.f, 153.f,
    212.f, 294.f, 406.f, 561.f, 776.f, 1072.f, 1482.f, 2048.f
};

// Weight fragments pre-packed in mma.m16n8k16 B-operand order (bf16x2 per reg).
__device__ uint32_t g_B0[2 * 8 * 64];   // W0: K=32 (2 ktiles), N=64 (8 ntiles)
__device__ uint32_t g_B1[4 * 8 * 64];   // W1: K=64, N=64
__device__ uint32_t g_B2[4 * 1 * 64];   // W2: K=64, N=3 (padded to 8)

// Feature scratch: 4 coalesced planes of uint4 (8 bf16 features each), 64 MB total.
__device__ __align__(16) uint4 g_feat[4][NPTS];

static __device__ __forceinline__ uint32_t pack_bf16(float lo, float hi) {
    uint32_t r;
    asm("cvt.rn.bf16x2.f32 %0, %1, %2;" : "=r"(r) : "f"(hi), "f"(lo));
    return r;
}

static __device__ __forceinline__ void ldmat4(uint32_t* r, const void* p) {
    uint32_t s = (uint32_t)__cvta_generic_to_shared(p);
    asm volatile("ldmatrix.sync.aligned.m8n8.x4.shared.b16 {%0,%1,%2,%3}, [%4];"
                 : "=r"(r[0]), "=r"(r[1]), "=r"(r[2]), "=r"(r[3]) : "r"(s));
}

static __device__ __forceinline__ void mma16816(float* c, const uint32_t* a, uint2 b) {
    asm volatile("mma.sync.aligned.m16n8k16.row.col.f32.bf16.bf16.f32 "
                 "{%0,%1,%2,%3}, {%4,%5,%6,%7}, {%8,%9}, {%0,%1,%2,%3};"
                 : "+f"(c[0]), "+f"(c[1]), "+f"(c[2]), "+f"(c[3])
                 : "r"(a[0]), "r"(a[1]), "r"(a[2]), "r"(a[3]), "r"(b.x), "r"(b.y));
}

// One-time (per launch) weight repack: fp32 [K][N] row-major -> bf16 frag order.
__global__ void prep_weights(const float* __restrict__ W0,
                             const float* __restrict__ W1,
                             const float* __restrict__ W2) {
    int i = blockIdx.x * blockDim.x + threadIdx.x;
    if (i < 1024) {
        int r = i & 1, lane = (i >> 1) & 31, nt = (i >> 6) & 7, kt = i >> 9;
        int tg = lane & 3, g = lane >> 2;
        int k = kt * 16 + tg * 2 + r * 8, n = nt * 8 + g;
        g_B0[i] = pack_bf16(W0[k * 64 + n], W0[(k + 1) * 64 + n]);
    } else if (i < 3072) {
        int j = i - 1024;
        int r = j & 1, lane = (j >> 1) & 31, nt = (j >> 6) & 7, kt = j >> 9;
        int tg = lane & 3, g = lane >> 2;
        int k = kt * 16 + tg * 2 + r * 8, n = nt * 8 + g;
        g_B1[j] = pack_bf16(W1[k * 64 + n], W1[(k + 1) * 64 + n]);
    } else if (i < 3328) {
        int j = i - 3072;
        int r = j & 1, lane = (j >> 1) & 31, kt = j >> 6;
        int tg = lane & 3, g = lane >> 2;
        int k = kt * 16 + tg * 2 + r * 8, n = g;
        float v0 = (n < 3) ? W2[k * 3 + n] : 0.f;
        float v1 = (n < 3) ? W2[(k + 1) * 3 + n] : 0.f;
        g_B2[j] = pack_bf16(v0, v1);
    }
}

// ---------------- kernel 1: hash-grid encode only ----------------
__global__ void __launch_bounds__(256, 4) ngp_encode(
    const float* __restrict__ x,
    const float* __restrict__ tables)
{
    const int n = blockIdx.x * 256 + threadIdx.x;
    const float2 p = __ldg((const float2*)x + n);

    uint32_t fpack[NLEV];
    #pragma unroll
    for (int l = 0; l < NLEV; l++) {
        const float res = c_res[l];
        float sx = p.x * res, sy = p.y * res;
        float fx = floorf(sx), fy = floorf(sy);
        float tx = sx - fx, ty = sy - fy;
        unsigned ux = (unsigned)(int)fx;
        unsigned uy = (unsigned)(int)fy;
        unsigned hy0 = uy * PRIME_Y;
        unsigned hy1 = (uy + 1u) * PRIME_Y;
        unsigned i00 = ( ux       ^ hy0) & (TBL - 1u);
        unsigned i10 = ((ux + 1u) ^ hy0) & (TBL - 1u);
        unsigned i01 = ( ux       ^ hy1) & (TBL - 1u);
        unsigned i11 = ((ux + 1u) ^ hy1) & (TBL - 1u);

        const float2* tb = (const float2*)tables + (size_t)l * TBL;
        float2 f00 = __ldg(tb + i00);
        float2 f10 = __ldg(tb + i10);
        float2 f01 = __ldg(tb + i01);
        float2 f11 = __ldg(tb + i11);

        float w00 = (1.f - tx) * (1.f - ty);
        float w10 = tx * (1.f - ty);
        float w01 = (1.f - tx) * ty;
        float w11 = tx * ty;

        float f0 = w00 * f00.x + w10 * f10.x + w01 * f01.x + w11 * f11.x;
        float f1 = w00 * f00.y + w10 * f10.y + w01 * f01.y + w11 * f11.y;
        fpack[l] = pack_bf16(f0, f1);
    }
    // 4 fully-coalesced 16B plane stores
    g_feat[0][n] = make_uint4(fpack[0],  fpack[1],  fpack[2],  fpack[3]);
    g_feat[1][n] = make_uint4(fpack[4],  fpack[5],  fpack[6],  fpack[7]);
    g_feat[2][n] = make_uint4(fpack[8],  fpack[9],  fpack[10], fpack[11]);
    g_feat[3][n] = make_uint4(fpack[12], fpack[13], fpack[14], fpack[15]);
}

// ---------------- kernel 2: MLP only ----------------
__global__ void __launch_bounds__(128, 5) ngp_mlp(
    const float* __restrict__ b0,
    const float* __restrict__ b1,
    const float* __restrict__ b2,
    float* __restrict__ out)
{
    // sA: feat rows (stride 80B) then layer1 output (stride 144B).
    // sB: layer0 output (stride 144B) then per-warp fp32 result staging.
    __shared__ __align__(16) unsigned char sA[128 * 144];
    __shared__ __align__(16) unsigned char sB[128 * 144];

    const int tid  = threadIdx.x;
    const int lane = tid & 31;
    const int w    = tid >> 5;
    const int tg   = lane & 3, g = lane >> 2;
    const int rowbase = w * 32;

    // ---- load features (coalesced) into mma staging layout ----
    const int n = blockIdx.x * 128 + tid;
    {
        uint4 v0 = __ldg(&g_feat[0][n]);
        uint4 v1 = __ldg(&g_feat[1][n]);
        uint4 v2 = __ldg(&g_feat[2][n]);
        uint4 v3 = __ldg(&g_feat[3][n]);
        uint4* dst = (uint4*)(sA + tid * 80);
        dst[0] = v0; dst[1] = v1; dst[2] = v2; dst[3] = v3;
    }
    __syncwarp();

    // ---- layer 0: [32] -> [64], relu  (sA/80 -> sB/144) ----
    #pragma unroll
    for (int mt = 0; mt < 2; mt++) {
        const int r0 = rowbase + mt * 16;
        uint32_t a[2][4];
        #pragma unroll
        for (int kt = 0; kt < 2; kt++)
            ldmat4(a[kt], sA + (r0 + (lane & 15)) * 80 + kt * 32 + (lane >> 4) * 16);
        float acc[8][4];
        #pragma unroll
        for (int nt = 0; nt < 8; nt++) {
            float2 bz = __ldg((const float2*)b0 + nt * 4 + tg);
            acc[nt][0] = bz.x; acc[nt][1] = bz.y;
            acc[nt][2] = bz.x; acc[nt][3] = bz.y;
        }
        #pragma unroll
        for (int kt = 0; kt < 2; kt++) {
            uint2 Bf[8];
            #pragma unroll
            for (int nt = 0; nt < 8; nt++)
                Bf[nt] = __ldg((const uint2*)g_B0 + (kt * 8 + nt) * 32 + lane);
            #pragma unroll
            for (int nt = 0; nt < 8; nt++)
                mma16816(acc[nt], a[kt], Bf[nt]);
        }
        #pragma unroll
        for (int nt = 0; nt < 8; nt++) {
            const int col = nt * 8 + tg * 2;
            *(uint32_t*)(sB + (r0 + g) * 144 + col * 2) =
                pack_bf16(fmaxf(acc[nt][0], 0.f), fmaxf(acc[nt][1], 0.f));
            *(uint32_t*)(sB + (r0 + g + 8) * 144 + col * 2) =
                pack_bf16(fmaxf(acc[nt][2], 0.f), fmaxf(acc[nt][3], 0.f));
        }
    }
    __syncwarp();

    // ---- layer 1: [64] -> [64], relu  (sB/144 -> sA/144) ----
    #pragma unroll
    for (int mt = 0; mt < 2; mt++) {
        const int r0 = rowbase + mt * 16;
        uint32_t a[4][4];
        #pragma unroll
        for (int kt = 0; kt < 4; kt++)
            ldmat4(a[kt], sB + (r0 + (lane & 15)) * 144 + kt * 32 + (lane >> 4) * 16);
        float acc[8][4];
        #pragma unroll
        for (int nt = 0; nt < 8; nt++) {
            float2 bz = __ldg((const float2*)b1 + nt * 4 + tg);
            acc[nt][0] = bz.x; acc[nt][1] = bz.y;
            acc[nt][2] = bz.x; acc[nt][3] = bz.y;
        }
        #pragma unroll
        for (int kt = 0; kt < 4; kt++) {
            uint2 Bf[8];
            #pragma unroll
            for (int nt = 0; nt < 8; nt++)
                Bf[nt] = __ldg((const uint2*)g_B1 + (kt * 8 + nt) * 32 + lane);
            #pragma unroll
            for (int nt = 0; nt < 8; nt++)
                mma16816(acc[nt], a[kt], Bf[nt]);
        }
        #pragma unroll
        for (int nt = 0; nt < 8; nt++) {
            const int col = nt * 8 + tg * 2;
            *(uint32_t*)(sA + (r0 + g) * 144 + col * 2) =
                pack_bf16(fmaxf(acc[nt][0], 0.f), fmaxf(acc[nt][1], 0.f));
            *(uint32_t*)(sA + (r0 + g + 8) * 144 + col * 2) =
                pack_bf16(fmaxf(acc[nt][2], 0.f), fmaxf(acc[nt][3], 0.f));
        }
    }
    __syncwarp();

    // ---- layer 2: [64] -> [3], sigmoid  (sA/144 -> warp-local fp32 staging) ----
    {
        uint2 Bf2[4];
        #pragma unroll
        for (int kt = 0; kt < 4; kt++)
            Bf2[kt] = __ldg((const uint2*)g_B2 + kt * 32 + lane);
        float bx = (tg == 0) ? __ldg(b2 + 0) : (tg == 1 ? __ldg(b2 + 2) : 0.f);
        float by = (tg == 0) ? __ldg(b2 + 1) : 0.f;

        unsigned char* osm = sB + w * (32 * 144);

        #pragma unroll
        for (int mt = 0; mt < 2; mt++) {
            const int r0 = rowbase + mt * 16;
            uint32_t a[4][4];
            #pragma unroll
            for (int kt = 0; kt < 4; kt++)
                ldmat4(a[kt], sA + (r0 + (lane & 15)) * 144 + kt * 32 + (lane >> 4) * 16);
            float acc[4] = {bx, by, bx, by};
            #pragma unroll
            for (int kt = 0; kt < 4; kt++)
                mma16816(acc, a[kt], Bf2[kt]);

            float s0 = 1.f / (1.f + __expf(-acc[0]));
            float s1 = 1.f / (1.f + __expf(-acc[1]));
            float s2 = 1.f / (1.f + __expf(-acc[2]));
            float s3 = 1.f / (1.f + __expf(-acc[3]));
            if (tg < 2) {
                const int lr = mt * 16 + g;
                *(float2*)(osm + lr * 16 + tg * 8)       = make_float2(s0, s1);
                *(float2*)(osm + (lr + 8) * 16 + tg * 8) = make_float2(s2, s3);
            }
        }
    }
    __syncwarp();

    // ---- coalesced store: 96 floats per warp ----
    {
        const float* osm = (const float*)(sB + w * (32 * 144));
        const int base = blockIdx.x * 384 + w * 96;
        #pragma unroll
        for (int k = 0; k < 3; k++) {
            const int j = lane + k * 32;              // 0..95
            out[base + j] = osm[(j / 3) * 4 + (j % 3)];
        }
    }
}

extern "C" void kernel_launch(void* const* d_in, const int* in_sizes, int n_in,
                              void* d_out, int out_size) {
    const float* x      = (const float*)d_in[0];
    const float* tables = (const float*)d_in[1];
    const float* W0     = (const float*)d_in[2];
    const float* b0     = (const float*)d_in[3];
    const float* W1     = (const float*)d_in[4];
    const float* b1     = (const float*)d_in[5];
    const float* W2     = (const float*)d_in[6];
    const float* b2     = (const float*)d_in[7];
    float* out = (float*)d_out;

    const int n = in_sizes[0] / 2;            // N points (1048576)
    prep_weights<<<13, 256>>>(W0, W1, W2);
    ngp_encode<<<n / 256, 256>>>(x, tables);
    ngp_mlp<<<n / 128, 128>>>(b0, b1, b2, out);
}

// round 8
// speedup vs baseline: 1.1922x; 1.1922x over previous
#include <cuda_runtime.h>
#include <cuda_bf16.h>
#include <cstdint>

#define NLEV 16
#define TBL 524288u
#define PRIME_Y 2654435761u

// floor(16 * 2^(7l/15)), l = 0..15 — matches numpy fp64 _resolutions()
__constant__ float c_res[NLEV] = {
    16.f, 22.f, 30.f, 42.f, 58.f, 80.f, 111.f, 153.f,
    212.f, 294.f, 406.f, 561.f, 776.f, 1072.f, 1482.f, 2048.f
};

// Weight fragments pre-packed in mma.m16n8k16 B-operand order (bf16x2 per reg).
__device__ uint32_t g_B0[2 * 8 * 64];   // W0: K=32 (2 ktiles), N=64 (8 ntiles)
__device__ uint32_t g_B1[4 * 8 * 64];   // W1: K=64, N=64
__device__ uint32_t g_B2[4 * 1 * 64];   // W2: K=64, N=3 (padded to 8)

static __device__ __forceinline__ uint32_t pack_bf16(float lo, float hi) {
    uint32_t r;
    asm("cvt.rn.bf16x2.f32 %0, %1, %2;" : "=r"(r) : "f"(hi), "f"(lo));
    return r;
}

static __device__ __forceinline__ void ldmat4(uint32_t* r, const void* p) {
    uint32_t s = (uint32_t)__cvta_generic_to_shared(p);
    asm volatile("ldmatrix.sync.aligned.m8n8.x4.shared.b16 {%0,%1,%2,%3}, [%4];"
                 : "=r"(r[0]), "=r"(r[1]), "=r"(r[2]), "=r"(r[3]) : "r"(s));
}

static __device__ __forceinline__ void mma16816(float* c, const uint32_t* a, uint2 b) {
    asm volatile("mma.sync.aligned.m16n8k16.row.col.f32.bf16.bf16.f32 "
                 "{%0,%1,%2,%3}, {%4,%5,%6,%7}, {%8,%9}, {%0,%1,%2,%3};"
                 : "+f"(c[0]), "+f"(c[1]), "+f"(c[2]), "+f"(c[3])
                 : "r"(a[0]), "r"(a[1]), "r"(a[2]), "r"(a[3]), "r"(b.x), "r"(b.y));
}

// 64-bit gather that the compiler treats as opaque (keeps issue order / batching).
static __device__ __forceinline__ float2 ldg_f2(const float2* p) {
    float2 v;
    asm volatile("ld.global.nc.v2.f32 {%0,%1}, [%2];"
                 : "=f"(v.x), "=f"(v.y) : "l"(p));
    return v;
}

// One-time (per launch) weight repack: fp32 [K][N] row-major -> bf16 frag order.
__global__ void prep_weights(const float* __restrict__ W0,
                             const float* __restrict__ W1,
                             const float* __restrict__ W2) {
    int i = blockIdx.x * blockDim.x + threadIdx.x;
    if (i < 1024) {
        int r = i & 1, lane = (i >> 1) & 31, nt = (i >> 6) & 7, kt = i >> 9;
        int tg = lane & 3, g = lane >> 2;
        int k = kt * 16 + tg * 2 + r * 8, n = nt * 8 + g;
        g_B0[i] = pack_bf16(W0[k * 64 + n], W0[(k + 1) * 64 + n]);
    } else if (i < 3072) {
        int j = i - 1024;
        int r = j & 1, lane = (j >> 1) & 31, nt = (j >> 6) & 7, kt = j >> 9;
        int tg = lane & 3, g = lane >> 2;
        int k = kt * 16 + tg * 2 + r * 8, n = nt * 8 + g;
        g_B1[j] = pack_bf16(W1[k * 64 + n], W1[(k + 1) * 64 + n]);
    } else if (i < 3328) {
        int j = i - 3072;
        int r = j & 1, lane = (j >> 1) & 31, kt = j >> 6;
        int tg = lane & 3, g = lane >> 2;
        int k = kt * 16 + tg * 2 + r * 8, n = g;
        float v0 = (n < 3) ? W2[k * 3 + n] : 0.f;
        float v1 = (n < 3) ? W2[(k + 1) * 3 + n] : 0.f;
        g_B2[j] = pack_bf16(v0, v1);
    }
}

__global__ void __launch_bounds__(128, 4) ngp_fused_mma(
    const float* __restrict__ x,
    const float* __restrict__ tables,
    const float* __restrict__ b0,
    const float* __restrict__ b1,
    const float* __restrict__ b2,
    float* __restrict__ out)
{
    __shared__ __align__(16) unsigned char sA[128 * 144];
    __shared__ __align__(16) unsigned char sB[128 * 144];

    const int tid  = threadIdx.x;
    const int lane = tid & 31;
    const int w    = tid >> 5;
    const int tg   = lane & 3, g = lane >> 2;
    const int rowbase = w * 32;

    // ---------------- hash-grid encode: two explicit phases per 8-level half ----------------
    // Phase A: issue ALL 32 corner loads of the half into a live register array (MLP ~32).
    // Phase B: consume. raw[][] being fully live blocks ptxas from sinking loads into FMAs.
    const int n = blockIdx.x * 128 + tid;
    const float2 p = __ldg((const float2*)x + n);

    uint32_t fpack[NLEV];
    #pragma unroll
    for (int half = 0; half < 2; half++) {
        float2 raw[8][4];
        float  txv[8], tyv[8];

        #pragma unroll
        for (int l8 = 0; l8 < 8; l8++) {
            const int l = half * 8 + l8;
            const float res = c_res[l];
            float sx = p.x * res, sy = p.y * res;
            float fx = floorf(sx), fy = floorf(sy);
            txv[l8] = sx - fx;  tyv[l8] = sy - fy;
            unsigned ux = (unsigned)(int)fx;
            unsigned uy = (unsigned)(int)fy;
            unsigned hy0 = uy * PRIME_Y;
            unsigned hy1 = (uy + 1u) * PRIME_Y;
            const float2* tb = (const float2*)tables + (size_t)l * TBL;
            raw[l8][0] = ldg_f2(tb + (( ux       ^ hy0) & (TBL - 1u)));
            raw[l8][1] = ldg_f2(tb + (((ux + 1u) ^ hy0) & (TBL - 1u)));
            raw[l8][2] = ldg_f2(tb + (( ux       ^ hy1) & (TBL - 1u)));
            raw[l8][3] = ldg_f2(tb + (((ux + 1u) ^ hy1) & (TBL - 1u)));
        }

        #pragma unroll
        for (int l8 = 0; l8 < 8; l8++) {
            const float tx = txv[l8], ty = tyv[l8];
            float w00 = (1.f - tx) * (1.f - ty);
            float w10 = tx * (1.f - ty);
            float w01 = (1.f - tx) * ty;
            float w11 = tx * ty;
            float f0 = w00 * raw[l8][0].x + w10 * raw[l8][1].x
                     + w01 * raw[l8][2].x + w11 * raw[l8][3].x;
            float f1 = w00 * raw[l8][0].y + w10 * raw[l8][1].y
                     + w01 * raw[l8][2].y + w11 * raw[l8][3].y;
            fpack[half * 8 + l8] = pack_bf16(f0, f1);
        }
    }
    {   // row tid, 32 bf16 cols, stride 80B (conflict-free for STS.128 & ldmatrix)
        uint4* dst = (uint4*)(sA + tid * 80);
        dst[0] = make_uint4(fpack[0],  fpack[1],  fpack[2],  fpack[3]);
        dst[1] = make_uint4(fpack[4],  fpack[5],  fpack[6],  fpack[7]);
        dst[2] = make_uint4(fpack[8],  fpack[9],  fpack[10], fpack[11]);
        dst[3] = make_uint4(fpack[12], fpack[13], fpack[14], fpack[15]);
    }
    __syncwarp();

    // ---------------- layer 0: [32] -> [64], relu  (sA/80 -> sB/144) ----------------
    #pragma unroll
    for (int mt = 0; mt < 2; mt++) {
        const int r0 = rowbase + mt * 16;
        uint32_t a[2][4];
        #pragma unroll
        for (int kt = 0; kt < 2; kt++)
            ldmat4(a[kt], sA + (r0 + (lane & 15)) * 80 + kt * 32 + (lane >> 4) * 16);
        float acc[8][4];
        #pragma unroll
        for (int nt = 0; nt < 8; nt++) {
            float2 bz = __ldg((const float2*)b0 + nt * 4 + tg);
            acc[nt][0] = bz.x; acc[nt][1] = bz.y;
            acc[nt][2] = bz.x; acc[nt][3] = bz.y;
        }
        #pragma unroll
        for (int kt = 0; kt < 2; kt++) {
            uint2 Bf[8];
            #pragma unroll
            for (int nt = 0; nt < 8; nt++)
                Bf[nt] = __ldg((const uint2*)g_B0 + (kt * 8 + nt) * 32 + lane);
            #pragma unroll
            for (int nt = 0; nt < 8; nt++)
                mma16816(acc[nt], a[kt], Bf[nt]);
        }
        #pragma unroll
        for (int nt = 0; nt < 8; nt++) {
            const int col = nt * 8 + tg * 2;
            *(uint32_t*)(sB + (r0 + g) * 144 + col * 2) =
                pack_bf16(fmaxf(acc[nt][0], 0.f), fmaxf(acc[nt][1], 0.f));
            *(uint32_t*)(sB + (r0 + g + 8) * 144 + col * 2) =
                pack_bf16(fmaxf(acc[nt][2], 0.f), fmaxf(acc[nt][3], 0.f));
        }
    }
    __syncwarp();

    // ---------------- layer 1: [64] -> [64], relu  (sB/144 -> sA/144) ----------------
    #pragma unroll
    for (int mt = 0; mt < 2; mt++) {
        const int r0 = rowbase + mt * 16;
        uint32_t a[4][4];
        #pragma unroll
        for (int kt = 0; kt < 4; kt++)
            ldmat4(a[kt], sB + (r0 + (lane & 15)) * 144 + kt * 32 + (lane >> 4) * 16);
        float acc[8][4];
        #pragma unroll
        for (int nt = 0; nt < 8; nt++) {
            float2 bz = __ldg((const float2*)b1 + nt * 4 + tg);
            acc[nt][0] = bz.x; acc[nt][1] = bz.y;
            acc[nt][2] = bz.x; acc[nt][3] = bz.y;
        }
        #pragma unroll
        for (int kt = 0; kt < 4; kt++) {
            uint2 Bf[8];
            #pragma unroll
            for (int nt = 0; nt < 8; nt++)
                Bf[nt] = __ldg((const uint2*)g_B1 + (kt * 8 + nt) * 32 + lane);
            #pragma unroll
            for (int nt = 0; nt < 8; nt++)
                mma16816(acc[nt], a[kt], Bf[nt]);
        }
        #pragma unroll
        for (int nt = 0; nt < 8; nt++) {
            const int col = nt * 8 + tg * 2;
            *(uint32_t*)(sA + (r0 + g) * 144 + col * 2) =
                pack_bf16(fmaxf(acc[nt][0], 0.f), fmaxf(acc[nt][1], 0.f));
            *(uint32_t*)(sA + (r0 + g + 8) * 144 + col * 2) =
                pack_bf16(fmaxf(acc[nt][2], 0.f), fmaxf(acc[nt][3], 0.f));
        }
    }
    __syncwarp();

    // ---------------- layer 2: [64] -> [3], sigmoid ----------------
    {
        uint2 Bf2[4];
        #pragma unroll
        for (int kt = 0; kt < 4; kt++)
            Bf2[kt] = __ldg((const uint2*)g_B2 + kt * 32 + lane);
        float bx = (tg == 0) ? __ldg(b2 + 0) : (tg == 1 ? __ldg(b2 + 2) : 0.f);
        float by = (tg == 0) ? __ldg(b2 + 1) : 0.f;

        unsigned char* osm = sB + w * (32 * 144);

        #pragma unroll
        for (int mt = 0; mt < 2; mt++) {
            const int r0 = rowbase + mt * 16;
            uint32_t a[4][4];
            #pragma unroll
            for (int kt = 0; kt < 4; kt++)
                ldmat4(a[kt], sA + (r0 + (lane & 15)) * 144 + kt * 32 + (lane >> 4) * 16);
            float acc[4] = {bx, by, bx, by};
            #pragma unroll
            for (int kt = 0; kt < 4; kt++)
                mma16816(acc, a[kt], Bf2[kt]);

            float s0 = 1.f / (1.f + __expf(-acc[0]));
            float s1 = 1.f / (1.f + __expf(-acc[1]));
            float s2 = 1.f / (1.f + __expf(-acc[2]));
            float s3 = 1.f / (1.f + __expf(-acc[3]));
            if (tg < 2) {
                const int lr = mt * 16 + g;
                *(float2*)(osm + lr * 16 + tg * 8)       = make_float2(s0, s1);
                *(float2*)(osm + (lr + 8) * 16 + tg * 8) = make_float2(s2, s3);
            }
        }
    }
    __syncwarp();

    // ---------------- coalesced store: 96 floats per warp ----------------
    {
        const float* osm = (const float*)(sB + w * (32 * 144));
        const int base = blockIdx.x * 384 + w * 96;
        #pragma unroll
        for (int k = 0; k < 3; k++) {
            const int j = lane + k * 32;              // 0..95
            out[base + j] = osm[(j / 3) * 4 + (j % 3)];
        }
    }
}

extern "C" void kernel_launch(void* const* d_in, const int* in_sizes, int n_in,
                              void* d_out, int out_size) {
    const float* x      = (const float*)d_in[0];
    const float* tables = (const float*)d_in[1];
    const float* W0     = (const float*)d_in[2];
    const float* b0     = (const float*)d_in[3];
    const float* W1     = (const float*)d_in[4];
    const float* b1     = (const float*)d_in[5];
    const float* W2     = (const float*)d_in[6];
    const float* b2     = (const float*)d_in[7];
    float* out = (float*)d_out;

    const int n = in_sizes[0] / 2;            // N points (1048576)
    prep_weights<<<13, 256>>>(W0, W1, W2);
    ngp_fused_mma<<<n / 128, 128>>>(x, tables, b0, b1, b2, out);
}